// round 16
// baseline (speedup 1.0000x reference)
#include <cuda_runtime.h>
#include <cuda_fp16.h>
#include <cstdint>
#include <math.h>

// LinearFullyConnectedGPLayer on sm_100 (legacy mma.sync fp16 path).
// R16 vs R15: k2 only -> CTA 128x256 (NT2=2), 8 warps of 64x64 tiles,
// 256 thr, 1 CTA/SM with full register headroom. Crossbar bytes/MMA
// 192->125, per-warp MMA ILP 2x. k1/k_tr/k_wround byte-identical to R15.

namespace {
constexpr int C    = 512;
constexpr int NB   = 8;
constexpr int MAXB = 16384;
constexpr int ROWS = MAXB * NB;

constexpr int TM   = 128;
constexpr int KC   = 64;            // K halves per stage
constexpr int NIT  = C / KC;        // 8
constexpr int NT1  = 8;             // k1 n-tiles (64 ch, L+R stacked)
constexpr int NT2  = 2;             // k2 n-tiles (256 ch each)

constexpr int PIT  = 80;            // halves per smem row
// k1 stage: A[128][80] + W[128][80]
constexpr int ST_W  = 128 * PIT;
constexpr int ST_SZ = 256 * PIT;    // 20480 halves
constexpr int K1_SMEM = 2 * ST_SZ * 2;       // 81920 B
constexpr int EPI_P  = 132;
// k2 stage: A[128][80] + W[256][80]
constexpr int ST2_W  = 128 * PIT;                  // 10240 halves
constexpr int ST2_SZ = 384 * PIT;                  // 30720 halves
constexpr int EPI_P2 = 260;
constexpr int K2_EPI_B = 128 * EPI_P2 * 4 + 16 * 256 * 4;   // 149504
constexpr int K2_SMEM  = K2_EPI_B;                 // > 2*ST2_SZ*2 = 122880
}

// ---- scratch (device globals; no allocation allowed) ----
__device__ __half g_a [(size_t)ROWS * C];
__device__ __half g_gp[(size_t)ROWS * C];
__device__ __half g_wl[(size_t)C * C];
__device__ __half g_wr[(size_t)C * C];
__device__ __half g_wo[(size_t)C * C];
__device__ float  g_normp[(size_t)MAXB * NT2];

// ---- helpers ----
__device__ __forceinline__ int p16(int k) {
    int g = k & 15, p = g >> 1, o = g & 1;
    int np = ((p & 3) << 1) | (p >> 2);
    return (k & ~15) | (np << 1) | o;
}
__device__ __forceinline__ uint32_t smem_u32(const void* p) {
    uint32_t a;
    asm("{ .reg .u64 t; cvta.to.shared.u64 t, %1; cvt.u32.u64 %0, t; }"
        : "=r"(a) : "l"(p));
    return a;
}
__device__ __forceinline__ void cp16(uint32_t dst, const void* src) {
    asm volatile("cp.async.cg.shared.global [%0], [%1], 16;"
                 :: "r"(dst), "l"(src) : "memory");
}
__device__ __forceinline__ void cp_commit() {
    asm volatile("cp.async.commit_group;" ::: "memory");
}
__device__ __forceinline__ void cp_wait1() {
    asm volatile("cp.async.wait_group 1;" ::: "memory");
}
__device__ __forceinline__ void cp_wait0() {
    asm volatile("cp.async.wait_group 0;" ::: "memory");
}
__device__ __forceinline__ void mma16(float (&c)[4], uint32_t a0, uint32_t a1,
                                      uint32_t a2, uint32_t a3,
                                      uint32_t b0, uint32_t b1) {
    asm volatile(
        "mma.sync.aligned.m16n8k16.row.col.f32.f16.f16.f32 "
        "{%0,%1,%2,%3}, {%4,%5,%6,%7}, {%8,%9}, {%0,%1,%2,%3};"
        : "+f"(c[0]), "+f"(c[1]), "+f"(c[2]), "+f"(c[3])
        : "r"(a0), "r"(a1), "r"(a2), "r"(a3), "r"(b0), "r"(b1));
}

// ============================================================================
// k_wround: fp16-round + K-interleave weights
// ============================================================================
__global__ void __launch_bounds__(256) k_wround(
    const float* __restrict__ WL, const float* __restrict__ WR,
    const float* __restrict__ WO)
{
    const int q = blockIdx.x * 256 + threadIdx.x;   // float4 index, 196608
    const int e = q * 4;
    const float* src;
    __half* dst;
    int m;
    if (e < 262144)       { src = WL + e;          dst = g_wl; m = e; }
    else if (e < 524288)  { src = WR + e - 262144; dst = g_wr; m = e - 262144; }
    else                  { src = WO + e - 524288; dst = g_wo; m = e - 524288; }
    const int r = m >> 9, c = m & 511;
    float4 v = *reinterpret_cast<const float4*>(src);
    dst[(size_t)r * C + p16(c + 0)] = __float2half_rn(v.x);
    dst[(size_t)r * C + p16(c + 1)] = __float2half_rn(v.y);
    dst[(size_t)r * C + p16(c + 2)] = __float2half_rn(v.z);
    dst[(size_t)r * C + p16(c + 3)] = __float2half_rn(v.w);
}

// ============================================================================
// k_tr: g_a[(b*8+i)*512 + p16(m)] = fp16(vec1[(b*512+m)*8 + i])
// ============================================================================
__global__ void __launch_bounds__(256) k_tr(const float* __restrict__ vec1) {
    __shared__ float smT[8][516];
    const int b = blockIdx.x;
    const int t = threadIdx.x;
    const float* src = vec1 + (size_t)b * C * NB;
#pragma unroll
    for (int u = 0; u < 4; ++u) {
        int q = t + 256 * u;             // float4 index 0..1023
        int m = q >> 1, ih = q & 1;
        float4 v = *reinterpret_cast<const float4*>(src + (size_t)m * 8 + ih * 4);
        smT[ih * 4 + 0][m] = v.x;
        smT[ih * 4 + 1][m] = v.y;
        smT[ih * 4 + 2][m] = v.z;
        smT[ih * 4 + 3][m] = v.w;
    }
    __syncthreads();
    __half* dst = g_a + (size_t)b * NB * C;
#pragma unroll
    for (int u = 0; u < 4; ++u) {
        int q = t + 256 * u;
        int i = q >> 7, mf = q & 127;
#pragma unroll
        for (int j = 0; j < 4; ++j) {
            int m = mf * 4 + j;
            dst[(size_t)i * C + p16(m)] = __float2half_rn(smT[i][m]);
        }
    }
}

// ============================================================================
// k1: O = A @ [WL-tile; WR-tile]^T -> bias + geometric product -> g_gp (fp16)
// grid (NT1, B/16), 256 thr, warps 2x4, warp tile 64x32.  (unchanged)
// ============================================================================
__global__ void __launch_bounds__(256, 2) k1(
    const float* __restrict__ bLp, const float* __restrict__ bRp)
{
    extern __shared__ char dsm[];
    __half* sh = reinterpret_cast<__half*>(dsm);
    const uint32_t sb = smem_u32(dsm);
    const int t = threadIdx.x;
    const int warp = t >> 5, lane = t & 31;
    const int wm = warp >> 2, wn = warp & 3;
    const int b0r = blockIdx.y * TM;
    const int n0  = blockIdx.x * 64;

    float acc[4][4][4] = {};

    auto load_stage = [&](int st) {
        const uint32_t base = sb + (uint32_t)((st & 1) * ST_SZ * 2);
        const int k0 = st * KC;
#pragma unroll
        for (int u = 0; u < 4; ++u) {               // A
            int idx = t + 256 * u;
            int row = idx >> 3, c4 = idx & 7;
            cp16(base + (uint32_t)((row * PIT + c4 * 8) * 2),
                 g_a + (size_t)(b0r + row) * C + k0 + c4 * 8);
        }
#pragma unroll
        for (int u = 0; u < 2; ++u) {               // WL rows 0-63
            int idx = t + 256 * u;
            int row = idx >> 3, c4 = idx & 7;
            cp16(base + (uint32_t)((ST_W + row * PIT + c4 * 8) * 2),
                 g_wl + (size_t)(n0 + row) * C + k0 + c4 * 8);
        }
#pragma unroll
        for (int u = 0; u < 2; ++u) {               // WR rows 64-127
            int idx = t + 256 * u;
            int row = idx >> 3, c4 = idx & 7;
            cp16(base + (uint32_t)((ST_W + (64 + row) * PIT + c4 * 8) * 2),
                 g_wr + (size_t)(n0 + row) * C + k0 + c4 * 8);
        }
        cp_commit();
    };
    auto compute = [&](int buf) {
        const __half* base = sh + buf * ST_SZ;
        const int q4 = 4 * (lane & 3);
        const __half* Ab = base + (wm * 64 + (lane >> 2)) * PIT + q4;
        const __half* Wb = base + ST_W + (wn * 32 + (lane >> 2)) * PIT + q4;
#pragma unroll
        for (int kk = 0; kk < KC; kk += 16) {
            uint2 av[4][2];
#pragma unroll
            for (int rf = 0; rf < 4; ++rf) {
                av[rf][0] = *reinterpret_cast<const uint2*>(Ab + (rf * 16    ) * PIT + kk);
                av[rf][1] = *reinterpret_cast<const uint2*>(Ab + (rf * 16 + 8) * PIT + kk);
            }
#pragma unroll
            for (int cf = 0; cf < 4; ++cf) {
                uint2 w = *reinterpret_cast<const uint2*>(Wb + cf * 8 * PIT + kk);
#pragma unroll
                for (int rf = 0; rf < 4; ++rf)
                    mma16(acc[rf][cf], av[rf][0].x, av[rf][1].x,
                          av[rf][0].y, av[rf][1].y, w.x, w.y);
            }
        }
    };
    load_stage(0);
    load_stage(1);
#pragma unroll 1
    for (int it = 0; it < NIT; ++it) {
        const int buf = it & 1;
        if (it >= NIT - 2) cp_wait0(); else cp_wait1();
        __syncthreads();
        compute(buf);
        __syncthreads();
        if (it + 2 < NIT) load_stage(it + 2);
    }

    // epilogue: acc -> Os[128][EPI_P] (cols 0-63 = L, 64-127 = R)
    float* Os = reinterpret_cast<float*>(dsm);
#pragma unroll
    for (int rf = 0; rf < 4; ++rf)
#pragma unroll
        for (int cf = 0; cf < 4; ++cf) {
            const int r = wm * 64 + rf * 16 + (lane >> 2);
            const int c = wn * 32 + cf * 8 + 2 * (lane & 3);
            *reinterpret_cast<float2*>(&Os[r * EPI_P + c]) =
                make_float2(acc[rf][cf][0], acc[rf][cf][1]);
            *reinterpret_cast<float2*>(&Os[(r + 8) * EPI_P + c]) =
                make_float2(acc[rf][cf][2], acc[rf][cf][3]);
        }
    __syncthreads();

    // bias + geometric product (Cl(3,0)) -> g_gp as fp16 (p16-interleaved col)
#pragma unroll
    for (int j = 0; j < 4; ++j) {
        const int p = t + 256 * j;          // 1024 (b,c) pairs
        const int b = p >> 6, c = p & 63;
        float L[8], R[8];
#pragma unroll
        for (int i = 0; i < 8; ++i) {
            L[i] = Os[(b * 8 + i) * EPI_P + c];
            R[i] = Os[(b * 8 + i) * EPI_P + c + 64];
        }
        L[0] += bLp[n0 + c];
        R[0] += bRp[n0 + c];
        float g[8];
        g[0] = L[0]*R[0] + L[1]*R[1] + L[2]*R[2] + L[3]*R[3] - L[4]*R[4] - L[5]*R[5] - L[6]*R[6] - L[7]*R[7];
        g[1] = L[1]*R[0] + L[0]*R[1] - L[2]*R[4] - L[3]*R[5] + L[4]*R[2] + L[5]*R[3] - L[6]*R[7] - L[7]*R[6];
        g[2] = L[0]*R[2] + L[2]*R[0] + L[1]*R[4] - L[4]*R[1] - L[3]*R[6] + L[6]*R[3] + L[5]*R[7] + L[7]*R[5];
        g[3] = L[0]*R[3] + L[3]*R[0] + L[1]*R[5] - L[5]*R[1] + L[2]*R[6] - L[6]*R[2] - L[4]*R[7] - L[7]*R[4];
        g[4] = L[0]*R[4] + L[4]*R[0] + L[1]*R[2] - L[2]*R[1] + L[3]*R[7] + L[7]*R[3] - L[5]*R[6] + L[6]*R[5];
        g[5] = L[0]*R[5] + L[5]*R[0] + L[1]*R[3] - L[3]*R[1] - L[2]*R[7] - L[7]*R[2] + L[4]*R[6] - L[6]*R[4];
        g[6] = L[0]*R[6] + L[6]*R[0] + L[2]*R[3] - L[3]*R[2] + L[1]*R[7] + L[7]*R[1] - L[4]*R[5] + L[5]*R[4];
        g[7] = L[0]*R[7] + L[7]*R[0] + L[1]*R[6] + L[6]*R[1] - L[2]*R[5] - L[5]*R[2] + L[3]*R[4] + L[4]*R[3];
        const int pc = n0 + p16(c);
#pragma unroll
        for (int i = 0; i < 8; ++i)
            g_gp[(size_t)(b0r + b * 8 + i) * C + pc] = __float2half_rn(g[i]);
    }
}

// ============================================================================
// k2: O = gp @ WO^T + bias; out (b,n,i); norm partials.
// grid (NT2=2, B/16), 256 thr, 8 warps 2x4, warp tile 64x64, CTA 128x256.
// ============================================================================
__global__ void __launch_bounds__(256, 1) k2(
    const float* __restrict__ bOp, float* __restrict__ outp)
{
    extern __shared__ char dsm[];
    __half* sh = reinterpret_cast<__half*>(dsm);
    const uint32_t sb = smem_u32(dsm);
    const int t = threadIdx.x;
    const int warp = t >> 5, lane = t & 31;
    const int wm = warp >> 2, wn = warp & 3;
    const int b0r = blockIdx.y * TM;
    const int b0b = blockIdx.y * 16;
    const int n0  = blockIdx.x * 256;

    float acc[4][8][4] = {};

    auto load_stage = [&](int st) {
        const uint32_t base = sb + (uint32_t)((st & 1) * ST2_SZ * 2);
        const int k0 = st * KC;
#pragma unroll
        for (int u = 0; u < 4; ++u) {               // A: 128 rows
            int idx = t + 256 * u;
            int row = idx >> 3, c4 = idx & 7;
            cp16(base + (uint32_t)((row * PIT + c4 * 8) * 2),
                 g_gp + (size_t)(b0r + row) * C + k0 + c4 * 8);
        }
#pragma unroll
        for (int u = 0; u < 8; ++u) {               // W: 256 rows
            int idx = t + 256 * u;
            int row = idx >> 3, c4 = idx & 7;
            cp16(base + (uint32_t)((ST2_W + row * PIT + c4 * 8) * 2),
                 g_wo + (size_t)(n0 + row) * C + k0 + c4 * 8);
        }
        cp_commit();
    };
    auto compute = [&](int buf) {
        const __half* base = sh + buf * ST2_SZ;
        const int q4 = 4 * (lane & 3);
        const __half* Ab = base + (wm * 64 + (lane >> 2)) * PIT + q4;
        const __half* Wb = base + ST2_W + (wn * 64 + (lane >> 2)) * PIT + q4;
#pragma unroll
        for (int kk = 0; kk < KC; kk += 16) {
            uint2 av[4][2];
#pragma unroll
            for (int rf = 0; rf < 4; ++rf) {
                av[rf][0] = *reinterpret_cast<const uint2*>(Ab + (rf * 16    ) * PIT + kk);
                av[rf][1] = *reinterpret_cast<const uint2*>(Ab + (rf * 16 + 8) * PIT + kk);
            }
#pragma unroll
            for (int cf = 0; cf < 8; ++cf) {
                uint2 w = *reinterpret_cast<const uint2*>(Wb + cf * 8 * PIT + kk);
#pragma unroll
                for (int rf = 0; rf < 4; ++rf)
                    mma16(acc[rf][cf], av[rf][0].x, av[rf][1].x,
                          av[rf][0].y, av[rf][1].y, w.x, w.y);
            }
        }
    };
    load_stage(0);
    load_stage(1);
#pragma unroll 1
    for (int it = 0; it < NIT; ++it) {
        const int buf = it & 1;
        if (it >= NIT - 2) cp_wait0(); else cp_wait1();
        __syncthreads();
        compute(buf);
        __syncthreads();
        if (it + 2 < NIT) load_stage(it + 2);
    }

    // epilogue: Os[128][EPI_P2] + Ns[16][256]
    float* Os = reinterpret_cast<float*>(dsm);
    float* Ns = Os + 128 * EPI_P2;
#pragma unroll
    for (int rf = 0; rf < 4; ++rf)
#pragma unroll
        for (int cf = 0; cf < 8; ++cf) {
            const int r = wm * 64 + rf * 16 + (lane >> 2);
            const int c = wn * 64 + cf * 8 + 2 * (lane & 3);
            *reinterpret_cast<float2*>(&Os[r * EPI_P2 + c]) =
                make_float2(acc[rf][cf][0], acc[rf][cf][1]);
            *reinterpret_cast<float2*>(&Os[(r + 8) * EPI_P2 + c]) =
                make_float2(acc[rf][cf][2], acc[rf][cf][3]);
        }
    __syncthreads();

#pragma unroll
    for (int j = 0; j < 16; ++j) {           // 4096 (b,c) pairs
        const int p = t + 256 * j;
        const int b = p >> 8, c = p & 255;
        const int nc = n0 + c;
        float o[8];
#pragma unroll
        for (int i = 0; i < 8; ++i) o[i] = Os[(b * 8 + i) * EPI_P2 + c];
        o[0] += bOp[nc];
        float ss = 0.f;
#pragma unroll
        for (int i = 0; i < 8; ++i) ss += o[i] * o[i];
        Ns[b * 256 + c] = sqrtf(ss);
        float* dst = outp + ((size_t)(b0b + b) * C + nc) * NB;
        *reinterpret_cast<float4*>(dst)     = make_float4(o[0], o[1], o[2], o[3]);
        *reinterpret_cast<float4*>(dst + 4) = make_float4(o[4], o[5], o[6], o[7]);
    }
    __syncthreads();

    // norm partial: warp w -> batches 2w, 2w+1 (sum over 256 cols)
#pragma unroll
    for (int bb = 0; bb < 2; ++bb) {
        const int b = warp * 2 + bb;
        float v = 0.f;
#pragma unroll
        for (int q = 0; q < 8; ++q) v += Ns[b * 256 + lane + 32 * q];
#pragma unroll
        for (int off = 16; off > 0; off >>= 1)
            v += __shfl_down_sync(0xffffffffu, v, off);
        if (lane == 0)
            g_normp[(size_t)(b0b + b) * NT2 + blockIdx.x] = v;
    }
}

// ============================================================================
// k_scale: out *= a_norm[c] / (mean_norm + eps); scale computed per block
// from the NT2 norm partials (fixed order -> deterministic).
// ============================================================================
__global__ void __launch_bounds__(256) k_scale(float* __restrict__ outp,
                                               const float* __restrict__ an) {
    __shared__ float s_scale;
    const int b = blockIdx.x >> 2;             // 4 blocks per batch
    if (threadIdx.x == 0) {
        float v = g_normp[(size_t)b * NT2 + 0] + g_normp[(size_t)b * NT2 + 1];
        s_scale = 1.f / (v * (1.f / (float)C) + 1e-6f);
    }
    __syncthreads();
    const size_t idx = (size_t)blockIdx.x * 256 + threadIdx.x;  // float4 index
    const int c = ((int)idx >> 1) & (C - 1);
    const float v = an[c] * s_scale;
    float4* o4 = reinterpret_cast<float4*>(outp) + idx;
    float4 w = *o4;
    w.x *= v; w.y *= v; w.z *= v; w.w *= v;
    *o4 = w;
}

// ============================================================================
extern "C" void kernel_launch(void* const* d_in, const int* in_sizes, int n_in,
                              void* d_out, int out_size) {
    const float* vec1 = (const float*)d_in[0];
    const float* WL   = (const float*)d_in[1];
    const float* bL   = (const float*)d_in[2];
    const float* WR   = (const float*)d_in[3];
    const float* bR   = (const float*)d_in[4];
    const float* WO   = (const float*)d_in[5];
    const float* bO   = (const float*)d_in[6];
    const float* an   = (const float*)d_in[7];
    float* out = (float*)d_out;

    int B = in_sizes[0] / (C * NB);   // 16384
    if (B > MAXB) B = MAXB;

    cudaFuncSetAttribute(k1, cudaFuncAttributeMaxDynamicSharedMemorySize, K1_SMEM);
    cudaFuncSetAttribute(k2, cudaFuncAttributeMaxDynamicSharedMemorySize, K2_SMEM);

    k_wround<<<768, 256>>>(WL, WR, WO);
    k_tr<<<B, 256>>>(vec1);
    dim3 g1(NT1, B / 16);
    dim3 g2(NT2, B / 16);
    k1<<<g1, 256, K1_SMEM>>>(bL, bR);
    k2<<<g2, 256, K2_SMEM>>>(bO, out);
    k_scale<<<(unsigned)((size_t)B * 4), 256>>>(out, an);
}

// round 17
// speedup vs baseline: 1.0832x; 1.0832x over previous
#include <cuda_runtime.h>
#include <cuda_fp16.h>
#include <cstdint>
#include <math.h>

// LinearFullyConnectedGPLayer on sm_100 (legacy mma.sync fp16 path).
// R17 = R12 exactly (best measured: 905.2us). Converged: the GEMMs run at
// the legacy HMMA pipe's instruction ceiling (~0.25 mma16/cyc/SM, ~272 TF/s;
// 50.4M mma16 -> 756us floor, measured 756us), invariant across warp count,
// tile shape, ILP and LDS-byte variations (R9/R11/R16). tcgen05 is rejected
// by the harness's -arch=sm_100 target (R5). Overhead kernels are at their
// DRAM rooflines; fusion regressed (R13).

namespace {
constexpr int C    = 512;
constexpr int NB   = 8;
constexpr int MAXB = 16384;
constexpr int ROWS = MAXB * NB;

constexpr int TM   = 128;
constexpr int KC   = 64;            // K halves per stage
constexpr int NIT  = C / KC;        // 8
constexpr int NT1  = 8;             // k1 n-tiles (64 ch, L+R stacked)
constexpr int NT2  = 4;             // k2 n-tiles (128 ch)

constexpr int PIT  = 80;            // halves per smem row
constexpr int ST_W  = 128 * PIT;
constexpr int ST_SZ = 256 * PIT;    // 20480 halves per stage
constexpr int K_SMEM = 2 * ST_SZ * 2;        // 81920 B
constexpr int EPI_P  = 132;
}

// ---- scratch (device globals; no allocation allowed) ----
__device__ __half g_a [(size_t)ROWS * C];
__device__ __half g_gp[(size_t)ROWS * C];
__device__ __half g_wl[(size_t)C * C];
__device__ __half g_wr[(size_t)C * C];
__device__ __half g_wo[(size_t)C * C];
__device__ float  g_normp[(size_t)MAXB * NT2];
__device__ float  g_scale[MAXB];

// ---- helpers ----
__device__ __forceinline__ int p16(int k) {
    int g = k & 15, p = g >> 1, o = g & 1;
    int np = ((p & 3) << 1) | (p >> 2);
    return (k & ~15) | (np << 1) | o;
}
__device__ __forceinline__ uint32_t smem_u32(const void* p) {
    uint32_t a;
    asm("{ .reg .u64 t; cvta.to.shared.u64 t, %1; cvt.u32.u64 %0, t; }"
        : "=r"(a) : "l"(p));
    return a;
}
__device__ __forceinline__ void cp16(uint32_t dst, const void* src) {
    asm volatile("cp.async.cg.shared.global [%0], [%1], 16;"
                 :: "r"(dst), "l"(src) : "memory");
}
__device__ __forceinline__ void cp_commit() {
    asm volatile("cp.async.commit_group;" ::: "memory");
}
__device__ __forceinline__ void cp_wait1() {
    asm volatile("cp.async.wait_group 1;" ::: "memory");
}
__device__ __forceinline__ void cp_wait0() {
    asm volatile("cp.async.wait_group 0;" ::: "memory");
}
__device__ __forceinline__ void mma16(float (&c)[4], uint32_t a0, uint32_t a1,
                                      uint32_t a2, uint32_t a3,
                                      uint32_t b0, uint32_t b1) {
    asm volatile(
        "mma.sync.aligned.m16n8k16.row.col.f32.f16.f16.f32 "
        "{%0,%1,%2,%3}, {%4,%5,%6,%7}, {%8,%9}, {%0,%1,%2,%3};"
        : "+f"(c[0]), "+f"(c[1]), "+f"(c[2]), "+f"(c[3])
        : "r"(a0), "r"(a1), "r"(a2), "r"(a3), "r"(b0), "r"(b1));
}

// ============================================================================
// k_wround: fp16-round + K-interleave weights
// ============================================================================
__global__ void __launch_bounds__(256) k_wround(
    const float* __restrict__ WL, const float* __restrict__ WR,
    const float* __restrict__ WO)
{
    const int q = blockIdx.x * 256 + threadIdx.x;   // float4 index, 196608
    const int e = q * 4;
    const float* src;
    __half* dst;
    int m;
    if (e < 262144)       { src = WL + e;          dst = g_wl; m = e; }
    else if (e < 524288)  { src = WR + e - 262144; dst = g_wr; m = e - 262144; }
    else                  { src = WO + e - 524288; dst = g_wo; m = e - 524288; }
    const int r = m >> 9, c = m & 511;
    float4 v = *reinterpret_cast<const float4*>(src);
    dst[(size_t)r * C + p16(c + 0)] = __float2half_rn(v.x);
    dst[(size_t)r * C + p16(c + 1)] = __float2half_rn(v.y);
    dst[(size_t)r * C + p16(c + 2)] = __float2half_rn(v.z);
    dst[(size_t)r * C + p16(c + 3)] = __float2half_rn(v.w);
}

// ============================================================================
// k_tr: g_a[(b*8+i)*512 + p16(m)] = fp16(vec1[(b*512+m)*8 + i])
// ============================================================================
__global__ void __launch_bounds__(256) k_tr(const float* __restrict__ vec1) {
    __shared__ float smT[8][516];
    const int b = blockIdx.x;
    const int t = threadIdx.x;
    const float* src = vec1 + (size_t)b * C * NB;
#pragma unroll
    for (int u = 0; u < 4; ++u) {
        int q = t + 256 * u;             // float4 index 0..1023
        int m = q >> 1, ih = q & 1;
        float4 v = *reinterpret_cast<const float4*>(src + (size_t)m * 8 + ih * 4);
        smT[ih * 4 + 0][m] = v.x;
        smT[ih * 4 + 1][m] = v.y;
        smT[ih * 4 + 2][m] = v.z;
        smT[ih * 4 + 3][m] = v.w;
    }
    __syncthreads();
    __half* dst = g_a + (size_t)b * NB * C;
#pragma unroll
    for (int u = 0; u < 4; ++u) {
        int q = t + 256 * u;
        int i = q >> 7, mf = q & 127;
#pragma unroll
        for (int j = 0; j < 4; ++j) {
            int m = mf * 4 + j;
            dst[(size_t)i * C + p16(m)] = __float2half_rn(smT[i][m]);
        }
    }
}

// ============================================================================
// k1: O = A @ [WL-tile; WR-tile]^T -> bias + geometric product -> g_gp (fp16)
// grid (NT1, B/16), 256 thr, warps 2x4, warp tile 64x32.
// ============================================================================
__global__ void __launch_bounds__(256, 2) k1(
    const float* __restrict__ bLp, const float* __restrict__ bRp)
{
    extern __shared__ char dsm[];
    __half* sh = reinterpret_cast<__half*>(dsm);
    const uint32_t sb = smem_u32(dsm);
    const int t = threadIdx.x;
    const int warp = t >> 5, lane = t & 31;
    const int wm = warp >> 2, wn = warp & 3;
    const int b0r = blockIdx.y * TM;
    const int n0  = blockIdx.x * 64;

    float acc[4][4][4] = {};

    auto load_stage = [&](int st) {
        const uint32_t base = sb + (uint32_t)((st & 1) * ST_SZ * 2);
        const int k0 = st * KC;
#pragma unroll
        for (int u = 0; u < 4; ++u) {               // A
            int idx = t + 256 * u;
            int row = idx >> 3, c4 = idx & 7;
            cp16(base + (uint32_t)((row * PIT + c4 * 8) * 2),
                 g_a + (size_t)(b0r + row) * C + k0 + c4 * 8);
        }
#pragma unroll
        for (int u = 0; u < 2; ++u) {               // WL rows 0-63
            int idx = t + 256 * u;
            int row = idx >> 3, c4 = idx & 7;
            cp16(base + (uint32_t)((ST_W + row * PIT + c4 * 8) * 2),
                 g_wl + (size_t)(n0 + row) * C + k0 + c4 * 8);
        }
#pragma unroll
        for (int u = 0; u < 2; ++u) {               // WR rows 64-127
            int idx = t + 256 * u;
            int row = idx >> 3, c4 = idx & 7;
            cp16(base + (uint32_t)((ST_W + (64 + row) * PIT + c4 * 8) * 2),
                 g_wr + (size_t)(n0 + row) * C + k0 + c4 * 8);
        }
        cp_commit();
    };
    auto compute = [&](int buf) {
        const __half* base = sh + buf * ST_SZ;
        const int q4 = 4 * (lane & 3);
        const __half* Ab = base + (wm * 64 + (lane >> 2)) * PIT + q4;
        const __half* Wb = base + ST_W + (wn * 32 + (lane >> 2)) * PIT + q4;
#pragma unroll
        for (int kk = 0; kk < KC; kk += 16) {
            uint2 av[4][2];
#pragma unroll
            for (int rf = 0; rf < 4; ++rf) {
                av[rf][0] = *reinterpret_cast<const uint2*>(Ab + (rf * 16    ) * PIT + kk);
                av[rf][1] = *reinterpret_cast<const uint2*>(Ab + (rf * 16 + 8) * PIT + kk);
            }
#pragma unroll
            for (int cf = 0; cf < 4; ++cf) {
                uint2 w = *reinterpret_cast<const uint2*>(Wb + cf * 8 * PIT + kk);
#pragma unroll
                for (int rf = 0; rf < 4; ++rf)
                    mma16(acc[rf][cf], av[rf][0].x, av[rf][1].x,
                          av[rf][0].y, av[rf][1].y, w.x, w.y);
            }
        }
    };
    load_stage(0);
    load_stage(1);
#pragma unroll 1
    for (int it = 0; it < NIT; ++it) {
        const int buf = it & 1;
        if (it >= NIT - 2) cp_wait0(); else cp_wait1();
        __syncthreads();
        compute(buf);
        __syncthreads();
        if (it + 2 < NIT) load_stage(it + 2);
    }

    // epilogue: acc -> Os[128][EPI_P] (cols 0-63 = L, 64-127 = R)
    float* Os = reinterpret_cast<float*>(dsm);
#pragma unroll
    for (int rf = 0; rf < 4; ++rf)
#pragma unroll
        for (int cf = 0; cf < 4; ++cf) {
            const int r = wm * 64 + rf * 16 + (lane >> 2);
            const int c = wn * 32 + cf * 8 + 2 * (lane & 3);
            *reinterpret_cast<float2*>(&Os[r * EPI_P + c]) =
                make_float2(acc[rf][cf][0], acc[rf][cf][1]);
            *reinterpret_cast<float2*>(&Os[(r + 8) * EPI_P + c]) =
                make_float2(acc[rf][cf][2], acc[rf][cf][3]);
        }
    __syncthreads();

    // bias + geometric product (Cl(3,0)) -> g_gp as fp16 (p16-interleaved col)
#pragma unroll
    for (int j = 0; j < 4; ++j) {
        const int p = t + 256 * j;          // 1024 (b,c) pairs
        const int b = p >> 6, c = p & 63;
        float L[8], R[8];
#pragma unroll
        for (int i = 0; i < 8; ++i) {
            L[i] = Os[(b * 8 + i) * EPI_P + c];
            R[i] = Os[(b * 8 + i) * EPI_P + c + 64];
        }
        L[0] += bLp[n0 + c];
        R[0] += bRp[n0 + c];
        float g[8];
        g[0] = L[0]*R[0] + L[1]*R[1] + L[2]*R[2] + L[3]*R[3] - L[4]*R[4] - L[5]*R[5] - L[6]*R[6] - L[7]*R[7];
        g[1] = L[1]*R[0] + L[0]*R[1] - L[2]*R[4] - L[3]*R[5] + L[4]*R[2] + L[5]*R[3] - L[6]*R[7] - L[7]*R[6];
        g[2] = L[0]*R[2] + L[2]*R[0] + L[1]*R[4] - L[4]*R[1] - L[3]*R[6] + L[6]*R[3] + L[5]*R[7] + L[7]*R[5];
        g[3] = L[0]*R[3] + L[3]*R[0] + L[1]*R[5] - L[5]*R[1] + L[2]*R[6] - L[6]*R[2] - L[4]*R[7] - L[7]*R[4];
        g[4] = L[0]*R[4] + L[4]*R[0] + L[1]*R[2] - L[2]*R[1] + L[3]*R[7] + L[7]*R[3] - L[5]*R[6] + L[6]*R[5];
        g[5] = L[0]*R[5] + L[5]*R[0] + L[1]*R[3] - L[3]*R[1] - L[2]*R[7] - L[7]*R[2] + L[4]*R[6] - L[6]*R[4];
        g[6] = L[0]*R[6] + L[6]*R[0] + L[2]*R[3] - L[3]*R[2] + L[1]*R[7] + L[7]*R[1] - L[4]*R[5] + L[5]*R[4];
        g[7] = L[0]*R[7] + L[7]*R[0] + L[1]*R[6] + L[6]*R[1] - L[2]*R[5] - L[5]*R[2] + L[3]*R[4] + L[4]*R[3];
        const int pc = n0 + p16(c);
#pragma unroll
        for (int i = 0; i < 8; ++i)
            g_gp[(size_t)(b0r + b * 8 + i) * C + pc] = __float2half_rn(g[i]);
    }
}

// ============================================================================
// k2: O = gp @ WO^T + bias; store out (b,n,i); norm partials -> g_normp
// grid (NT2, B/16), 256 thr.
// ============================================================================
__global__ void __launch_bounds__(256, 2) k2(
    const float* __restrict__ bOp, float* __restrict__ outp)
{
    extern __shared__ char dsm[];
    __half* sh = reinterpret_cast<__half*>(dsm);
    const uint32_t sb = smem_u32(dsm);
    const int t = threadIdx.x;
    const int warp = t >> 5, lane = t & 31;
    const int wm = warp >> 2, wn = warp & 3;
    const int b0r = blockIdx.y * TM;
    const int b0b = blockIdx.y * 16;
    const int n0  = blockIdx.x * 128;

    float acc[4][4][4] = {};

    auto load_stage = [&](int st) {
        const uint32_t base = sb + (uint32_t)((st & 1) * ST_SZ * 2);
        const int k0 = st * KC;
#pragma unroll
        for (int u = 0; u < 4; ++u) {               // A
            int idx = t + 256 * u;
            int row = idx >> 3, c4 = idx & 7;
            cp16(base + (uint32_t)((row * PIT + c4 * 8) * 2),
                 g_gp + (size_t)(b0r + row) * C + k0 + c4 * 8);
        }
#pragma unroll
        for (int u = 0; u < 4; ++u) {               // W
            int idx = t + 256 * u;
            int row = idx >> 3, c4 = idx & 7;
            cp16(base + (uint32_t)((ST_W + row * PIT + c4 * 8) * 2),
                 g_wo + (size_t)(n0 + row) * C + k0 + c4 * 8);
        }
        cp_commit();
    };
    auto compute = [&](int buf) {
        const __half* base = sh + buf * ST_SZ;
        const int q4 = 4 * (lane & 3);
        const __half* Ab = base + (wm * 64 + (lane >> 2)) * PIT + q4;
        const __half* Wb = base + ST_W + (wn * 32 + (lane >> 2)) * PIT + q4;
#pragma unroll
        for (int kk = 0; kk < KC; kk += 16) {
            uint2 av[4][2];
#pragma unroll
            for (int rf = 0; rf < 4; ++rf) {
                av[rf][0] = *reinterpret_cast<const uint2*>(Ab + (rf * 16    ) * PIT + kk);
                av[rf][1] = *reinterpret_cast<const uint2*>(Ab + (rf * 16 + 8) * PIT + kk);
            }
#pragma unroll
            for (int cf = 0; cf < 4; ++cf) {
                uint2 w = *reinterpret_cast<const uint2*>(Wb + cf * 8 * PIT + kk);
#pragma unroll
                for (int rf = 0; rf < 4; ++rf)
                    mma16(acc[rf][cf], av[rf][0].x, av[rf][1].x,
                          av[rf][0].y, av[rf][1].y, w.x, w.y);
            }
        }
    };
    load_stage(0);
    load_stage(1);
#pragma unroll 1
    for (int it = 0; it < NIT; ++it) {
        const int buf = it & 1;
        if (it >= NIT - 2) cp_wait0(); else cp_wait1();
        __syncthreads();
        compute(buf);
        __syncthreads();
        if (it + 2 < NIT) load_stage(it + 2);
    }

    // epilogue: Os[128][EPI_P] + Ns[16][128]
    float* Os = reinterpret_cast<float*>(dsm);
    float* Ns = Os + 128 * EPI_P;
#pragma unroll
    for (int rf = 0; rf < 4; ++rf)
#pragma unroll
        for (int cf = 0; cf < 4; ++cf) {
            const int r = wm * 64 + rf * 16 + (lane >> 2);
            const int c = wn * 32 + cf * 8 + 2 * (lane & 3);
            *reinterpret_cast<float2*>(&Os[r * EPI_P + c]) =
                make_float2(acc[rf][cf][0], acc[rf][cf][1]);
            *reinterpret_cast<float2*>(&Os[(r + 8) * EPI_P + c]) =
                make_float2(acc[rf][cf][2], acc[rf][cf][3]);
        }
    __syncthreads();

#pragma unroll
    for (int j = 0; j < 8; ++j) {            // 2048 (b,c) pairs
        const int p = t + 256 * j;
        const int b = p >> 7, c = p & 127;
        const int nc = n0 + c;
        float o[8];
#pragma unroll
        for (int i = 0; i < 8; ++i) o[i] = Os[(b * 8 + i) * EPI_P + c];
        o[0] += bOp[nc];
        float ss = 0.f;
#pragma unroll
        for (int i = 0; i < 8; ++i) ss += o[i] * o[i];
        Ns[b * 128 + c] = sqrtf(ss);
        float* dst = outp + ((size_t)(b0b + b) * C + nc) * NB;
        *reinterpret_cast<float4*>(dst)     = make_float4(o[0], o[1], o[2], o[3]);
        *reinterpret_cast<float4*>(dst + 4) = make_float4(o[4], o[5], o[6], o[7]);
    }
    __syncthreads();

    // norm partial: warp w -> batches 2w, 2w+1
#pragma unroll
    for (int bb = 0; bb < 2; ++bb) {
        const int b = warp * 2 + bb;
        float v = Ns[b * 128 + lane] + Ns[b * 128 + lane + 32] +
                  Ns[b * 128 + lane + 64] + Ns[b * 128 + lane + 96];
#pragma unroll
        for (int off = 16; off > 0; off >>= 1)
            v += __shfl_down_sync(0xffffffffu, v, off);
        if (lane == 0)
            g_normp[(size_t)(b0b + b) * NT2 + blockIdx.x] = v;
    }
}

// ============================================================================
__global__ void __launch_bounds__(256) k_red(int B) {
    const int b = blockIdx.x * 256 + threadIdx.x;
    if (b < B) {
        float v = 0.f;
#pragma unroll
        for (int j = 0; j < NT2; ++j) v += g_normp[(size_t)b * NT2 + j];
        g_scale[b] = 1.f / (v * (1.f / (float)C) + 1e-6f);
    }
}

__global__ void __launch_bounds__(256) k_scale(float* __restrict__ outp,
                                               const float* __restrict__ an) {
    const size_t idx = (size_t)blockIdx.x * 256 + threadIdx.x;  // float4 index
    const int b = (int)(idx >> 10);
    const int c = ((int)idx >> 1) & (C - 1);
    const float v = an[c] * g_scale[b];
    float4* o4 = reinterpret_cast<float4*>(outp) + idx;
    float4 w = *o4;
    w.x *= v; w.y *= v; w.z *= v; w.w *= v;
    *o4 = w;
}

// ============================================================================
extern "C" void kernel_launch(void* const* d_in, const int* in_sizes, int n_in,
                              void* d_out, int out_size) {
    const float* vec1 = (const float*)d_in[0];
    const float* WL   = (const float*)d_in[1];
    const float* bL   = (const float*)d_in[2];
    const float* WR   = (const float*)d_in[3];
    const float* bR   = (const float*)d_in[4];
    const float* WO   = (const float*)d_in[5];
    const float* bO   = (const float*)d_in[6];
    const float* an   = (const float*)d_in[7];
    float* out = (float*)d_out;

    int B = in_sizes[0] / (C * NB);   // 16384
    if (B > MAXB) B = MAXB;

    cudaFuncSetAttribute(k1, cudaFuncAttributeMaxDynamicSharedMemorySize, K_SMEM);
    cudaFuncSetAttribute(k2, cudaFuncAttributeMaxDynamicSharedMemorySize, K_SMEM);

    k_wround<<<768, 256>>>(WL, WR, WO);
    k_tr<<<B, 256>>>(vec1);
    dim3 g1(NT1, B / 16);
    dim3 g2(NT2, B / 16);
    k1<<<g1, 256, K_SMEM>>>(bL, bR);
    k2<<<g2, 256, K_SMEM>>>(bO, out);
    k_red<<<(B + 255) / 256, 256>>>(B);
    k_scale<<<(unsigned)((size_t)B * 1024 / 256), 256>>>(out, an);
}